// round 16
// baseline (speedup 1.0000x reference)
#include <cuda_runtime.h>
#include <cuda_fp16.h>
#include <cstdint>

#define NNODES 50000
#define NEDGE  800000
#define ETOT   850000
#define DIM    128
#define NH     4
#define NB     7
#define KDIM   1024
#define NGR    64
#define NCLS   10
#define NLAYER 3

#define MTILES ((NNODES + 127) / 128)   // 391
#define SCAN_BLOCKS ((NNODES + 1023) / 1024)  // 49
#define POOL_CHUNKS ((NNODES + 511) / 512)    // 98

// ---------------- device scratch ----------------
__device__ __align__(16) __half g_W16[NLAYER * KDIM * DIM];
__device__ __align__(16) float g_h[NNODES * DIM];
__device__ __align__(16) __half g_hl16[NNODES * DIM];
__device__ __align__(16) float g_asrc[NNODES * NH];
__device__ __align__(16) float g_adst[NNODES * NH];
__device__ __align__(16) float g_pooled[NGR * DIM];
// CSR
__device__ int g_deg[NNODES];
__device__ int g_ptr[NNODES + 1];
__device__ int g_cur[NNODES];
__device__ int g_csrc[ETOT];
__device__ int g_bsum[SCAN_BLOCKS];
__device__ int g_boff[SCAN_BLOCKS];
// global barrier
__device__ int g_bar_count;
__device__ int g_bar_gen;

// ---------------- helpers ----------------
__device__ __forceinline__ uint32_t smem_u32(const void* p) {
    uint32_t a;
    asm("{ .reg .u64 t; cvta.to.shared.u64 t, %1; cvt.u32.u64 %0, t; }" : "=r"(a) : "l"(p));
    return a;
}

#define SWZ32(c, r) (((c) ^ ((r) >> 1)) & 3)

__device__ __forceinline__ void ldsm4(uint32_t a, uint32_t& r0, uint32_t& r1,
                                      uint32_t& r2, uint32_t& r3) {
    asm volatile("ldmatrix.sync.aligned.m8n8.x4.shared.b16 {%0,%1,%2,%3}, [%4];"
                 : "=r"(r0), "=r"(r1), "=r"(r2), "=r"(r3) : "r"(a));
}

__device__ __forceinline__ void mma16816(float* d, const uint32_t* a, const uint32_t* b) {
    asm volatile("mma.sync.aligned.m16n8k16.row.col.f32.f16.f16.f32 "
                 "{%0,%1,%2,%3}, {%4,%5,%6,%7}, {%8,%9}, {%0,%1,%2,%3};"
                 : "+f"(d[0]), "+f"(d[1]), "+f"(d[2]), "+f"(d[3])
                 : "r"(a[0]), "r"(a[1]), "r"(a[2]), "r"(a[3]), "r"(b[0]), "r"(b[1]));
}

__device__ __forceinline__ float silu_f(float x) { return x / (1.0f + __expf(-x)); }

// Cox-de Boor recursion (used only in readout)
__device__ __forceinline__ void bsplines7(float x, float* out) {
    float b0[10];
#pragma unroll
    for (int i = 0; i < 10; i++) {
        float g0 = 0.5f * (float)i - 2.5f;
        b0[i] = (x >= g0 && x < g0 + 0.5f) ? 1.0f : 0.0f;
    }
    float b1[9];
#pragma unroll
    for (int i = 0; i < 9; i++) {
        float gi = 0.5f * (float)i - 2.5f;
        b1[i] = (x - gi) * 2.0f * b0[i] + ((gi + 1.0f) - x) * 2.0f * b0[i + 1];
    }
    float b2[8];
#pragma unroll
    for (int i = 0; i < 8; i++) {
        float gi = 0.5f * (float)i - 2.5f;
        b2[i] = (x - gi) * b1[i] + ((gi + 1.5f) - x) * b1[i + 1];
    }
#pragma unroll
    for (int i = 0; i < 7; i++) {
        float gi = 0.5f * (float)i - 2.5f;
        out[i] = ((x - gi) * b2[i] + ((gi + 2.0f) - x) * b2[i + 1]) * (1.0f / 1.5f);
    }
}

__device__ __forceinline__ uint32_t pack_f16x2(float a, float b) {
    uint32_t r;
    asm("cvt.rn.f16x2.f32 %0, %1, %2;" : "=r"(r) : "f"(b), "f"(a));
    return r;
}

// software global barrier; __threadfence also invalidates L1D on sm_103a
__device__ __forceinline__ void gbar(int nb, int& gen) {
    __syncthreads();
    if (threadIdx.x == 0) {
        __threadfence();
        if (atomicAdd(&g_bar_count, 1) == nb - 1) {
            g_bar_count = 0;
            __threadfence();
            atomicExch(&g_bar_gen, gen + 1);
        } else {
            while (*(volatile int*)&g_bar_gen == gen) __nanosleep(64);
            __threadfence();
        }
    }
    __syncthreads();
    gen++;
}

// ---------------- CSR build ----------------
__global__ void deg_count_kernel(const int* __restrict__ ei) {
    int e = blockIdx.x * blockDim.x + threadIdx.x;
    if (e >= ETOT) return;
    int d = (e < NEDGE) ? __ldg(&ei[NEDGE + e]) : (e - NEDGE);
    atomicAdd(&g_deg[d], 1);
}

__global__ void scan1_kernel() {
    __shared__ int sh[1024];
    int t = threadIdx.x, b = blockIdx.x;
    int i = b * 1024 + t;
    int v = (i < NNODES) ? g_deg[i] : 0;
    sh[t] = v;
    __syncthreads();
#pragma unroll
    for (int off = 1; off < 1024; off <<= 1) {
        int add = (t >= off) ? sh[t - off] : 0;
        __syncthreads();
        sh[t] += add;
        __syncthreads();
    }
    if (i < NNODES) g_ptr[i] = sh[t] - v;
    if (t == 1023) g_bsum[b] = sh[t];
}

__global__ void scan2_kernel() {
    if (threadIdx.x == 0) {
        int run = 0;
        for (int b = 0; b < SCAN_BLOCKS; b++) { g_boff[b] = run; run += g_bsum[b]; }
        g_ptr[NNODES] = run;
    }
}

__global__ void scan3_kernel() {
    int t = threadIdx.x, b = blockIdx.x;
    int i = b * 1024 + t;
    if (i < NNODES) {
        int p = g_ptr[i] + g_boff[b];
        g_ptr[i] = p;
        g_cur[i] = p;
    }
}

__global__ void scatter_kernel(const int* __restrict__ ei) {
    int e = blockIdx.x * blockDim.x + threadIdx.x;
    if (e >= ETOT) return;
    int s, d;
    if (e < NEDGE) { s = __ldg(&ei[e]); d = __ldg(&ei[NEDGE + e]); }
    else           { s = e - NEDGE; d = s; }
    int pos = atomicAdd(&g_cur[d], 1);
    g_csrc[pos] = s;
}

// ---------------- weight pack (all 3 layers, once, fp16) ----------------
__global__ void pack_w_kernel(const float* __restrict__ bw,
                              const float* __restrict__ sw,
                              const float* __restrict__ sc) {
    int idx = blockIdx.x * blockDim.x + threadIdx.x;
    if (idx >= NLAYER * KDIM * DIM) return;
    int l = idx >> 17;
    int rem = idx & (KDIM * DIM - 1);
    int n = rem >> 10, k = rem & 1023;
    int j = k >> 3, f = k & 7;
    const float* bwl = bw + (size_t)l * DIM * DIM;
    const float* swl = sw + (size_t)l * DIM * DIM * NB;
    const float* scl = sc + (size_t)l * DIM * DIM;
    float v;
    if (f == 0) v = bwl[n * DIM + j];
    else        v = swl[(n * DIM + j) * NB + (f - 1)] * scl[n * DIM + j];
    g_W16[idx] = __float2half_rn(v);
}

// ---------------- GEMM tile body (fp16 mma, pipelined double-buffered) ----------------
#define SMEM_BYTES 32768

__device__ __forceinline__ void build_chunk(const float* __restrict__ in,
                                            const __half* __restrict__ W16,
                                            char* buf, int m0, int tid, int cc, bool rvalid) {
    char* Ab = buf;
    char* Bb = buf + 8192;

    int n = tid >> 1, half = tid & 1;
    const uint4* wh = (const uint4*)(W16 + (size_t)n * KDIM + cc * 32 + half * 16);
    uint4 bh0 = wh[0], bh1 = wh[1];

    int row = tid & 127, jp = tid >> 7;
    float2 xv2 = rvalid ? *(const float2*)(in + (size_t)(m0 + row) * DIM + cc * 4 + jp * 2)
                        : make_float2(0.f, 0.f);
#pragma unroll
    for (int q = 0; q < 2; q++) {
        float xv = q ? xv2.y : xv2.x;
        int cch = jp * 2 + q;
        uint32_t off = row * 64 + (SWZ32(cch, row) << 4);

        float sv = silu_f(xv);
        uint32_t sp = pack_f16x2(sv, 0.0f);
        *(uint4*)(Ab + off) = make_uint4(sp & 0xFFFFu, 0u, 0u, 0u);

        float u = fmaf(2.0f, xv, 5.0f);
        float cf = floorf(u);
        float t = u - cf;
        bool inr = (u >= 0.0f) && (u < 10.0f);
        int c = (int)cf;
        float t2 = t * t, t3 = t2 * t, s1 = 1.0f - t;
        const float i6 = 1.0f / 6.0f;
        float w[4];
        w[0] = t3 * i6;
        w[1] = fmaf(-3.0f, t3, fmaf(3.0f, t2, fmaf(3.0f, t, 1.0f))) * i6;
        w[2] = fmaf(3.0f, t3, fmaf(-6.0f, t2, 4.0f)) * i6;
        w[3] = s1 * s1 * s1 * i6;
#pragma unroll
        for (int m = 0; m < 4; m++) {
            int j = c - m;
            if (inr && j >= 0 && j <= 6) {
                __half hw = __float2half_rn(w[m]);
                *(uint16_t*)(Ab + off + 2 * (j + 1)) = __half_as_ushort(hw);
            }
        }
    }
#pragma unroll
    for (int q = 0; q < 2; q++) {
        int c = half * 2 + q;
        uint32_t off = n * 64 + (SWZ32(c, n) << 4);
        *(uint4*)(Bb + off) = q ? bh1 : bh0;
    }
}

__device__ __forceinline__ void gemm_tile_body(const float* __restrict__ in,
                                               const float* __restrict__ attS,
                                               const float* __restrict__ attD,
                                               const __half* __restrict__ W16,
                                               char* dsm, int m0) {
    int tid = threadIdx.x;
    int wid = tid >> 5, lane = tid & 31;
    int warpM = wid & 3, warpN = wid >> 2;
    uint32_t ubase = smem_u32(dsm);

    bool rvalid = (m0 + (tid & 127)) < NNODES;
    int tg = lane >> 3, tr = lane & 7;

    float acc[2][8][4];
#pragma unroll
    for (int f = 0; f < 2; f++)
#pragma unroll
        for (int j = 0; j < 8; j++)
#pragma unroll
            for (int q = 0; q < 4; q++) acc[f][j][q] = 0.0f;

    build_chunk(in, W16, dsm, m0, tid, 0, rvalid);
    __syncthreads();

    for (int cc = 0; cc < 32; cc++) {
        int p = cc & 1;
        uint32_t uA = ubase + p * 16384;
        uint32_t uB = uA + 8192;

#pragma unroll
        for (int ks = 0; ks < 2; ks++) {
            uint32_t ah[2][4];
#pragma unroll
            for (int f = 0; f < 2; f++) {
                int arow = warpM * 32 + f * 16 + (tg & 1) * 8 + tr;
                int ac = ks * 2 + (tg >> 1);
                uint32_t aoff = arow * 64 + (SWZ32(ac, arow) << 4);
                ldsm4(uA + aoff, ah[f][0], ah[f][1], ah[f][2], ah[f][3]);
            }
#pragma unroll
            for (int gh = 0; gh < 2; gh++) {
                uint32_t bh[2][4];
#pragma unroll
                for (int gg = 0; gg < 2; gg++) {
                    int g = gh * 2 + gg;
                    int brow = warpN * 64 + g * 16 + (tg >> 1) * 8 + tr;
                    int bc = ks * 2 + (tg & 1);
                    uint32_t boff = brow * 64 + (SWZ32(bc, brow) << 4);
                    ldsm4(uB + boff, bh[gg][0], bh[gg][1], bh[gg][2], bh[gg][3]);
                }
#pragma unroll
                for (int f = 0; f < 2; f++)
#pragma unroll
                    for (int gg = 0; gg < 2; gg++) {
                        int g = gh * 2 + gg;
                        mma16816(acc[f][2 * g],     ah[f], &bh[gg][0]);
                        mma16816(acc[f][2 * g + 1], ah[f], &bh[gg][2]);
                    }
            }
        }

        if (cc < 31)
            build_chunk(in, W16, dsm + (p ^ 1) * 16384, m0, tid, cc + 1, rvalid);
        __syncthreads();
    }

    int qd = lane >> 2, ql = lane & 3;
#pragma unroll
    for (int f = 0; f < 2; f++)
#pragma unroll
        for (int hh = 0; hh < 2; hh++) {
            int row = m0 + warpM * 32 + f * 16 + hh * 8 + qd;
            bool ok = row < NNODES;
            float ps0 = 0.f, pd0 = 0.f, ps1 = 0.f, pd1 = 0.f;
#pragma unroll
            for (int j = 0; j < 8; j++) {
                int col = warpN * 64 + j * 8 + ql * 2;
                float v0 = acc[f][j][hh * 2 + 0];
                float v1 = acc[f][j][hh * 2 + 1];
                if (ok) {
                    __half2 hv = __floats2half2_rn(v0, v1);
                    *(__half2*)&g_hl16[(size_t)row * DIM + col] = hv;
                }
                float s0 = __ldg(&attS[col]), s1 = __ldg(&attS[col + 1]);
                float d0 = __ldg(&attD[col]), d1 = __ldg(&attD[col + 1]);
                float ps = v0 * s0 + v1 * s1;
                float pd = v0 * d0 + v1 * d1;
                if (j < 4) { ps0 += ps; pd0 += pd; } else { ps1 += ps; pd1 += pd; }
            }
#pragma unroll
            for (int o = 1; o <= 2; o <<= 1) {
                ps0 += __shfl_xor_sync(0xffffffffu, ps0, o);
                pd0 += __shfl_xor_sync(0xffffffffu, pd0, o);
                ps1 += __shfl_xor_sync(0xffffffffu, ps1, o);
                pd1 += __shfl_xor_sync(0xffffffffu, pd1, o);
            }
            if (ql == 0 && ok) {
                int hbase = warpN * 2;
                g_asrc[row * 4 + hbase]     = ps0;
                g_asrc[row * 4 + hbase + 1] = ps1;
                g_adst[row * 4 + hbase]     = pd0;
                g_adst[row * 4 + hbase + 1] = pd1;
            }
        }
}

// standalone layer-0 GEMM (overlaps side-stream CSR build)
__global__ void __launch_bounds__(256, 2) fkan_gemm_mma(const float* __restrict__ in,
                                                        const float* __restrict__ attS,
                                                        const float* __restrict__ attD,
                                                        const __half* __restrict__ W16) {
    extern __shared__ char dsm[];
    gemm_tile_body(in, attS, attD, W16, dsm, blockIdx.x * 128);
}

// ---------------- edge body (split-lane, 2 edges per warp iter) ----------------
__device__ __forceinline__ void edge_node_body(const float* __restrict__ bias, int n, int lane) {
    int start = __ldg(&g_ptr[n]);
    int end   = __ldg(&g_ptr[n + 1]);
    int hw = lane >> 4;
    int lw = lane & 15;
    int hh = lw >> 2;
    float bd = g_adst[n * 4 + hh];

    float acc[8];
#pragma unroll
    for (int j = 0; j < 8; j++) acc[j] = 0.0f;
    float sumex = 0.0f;

    for (int j0 = start; j0 < end; j0 += 32) {
        int m = min(32, end - j0);
        int s_pref = (j0 + lane < end) ? __ldg(&g_csrc[j0 + lane]) : 0;
#pragma unroll 4
        for (int i = 0; i < m; i += 2) {
            int idx = i + hw;
            int s = __shfl_sync(0xffffffffu, s_pref, idx & 31);
            if (idx < m) {
                float a = __ldg(&g_asrc[s * 4 + hh]);
                float e = a + bd;
                e = (e > 0.f) ? e : 0.2f * e;
                float ex = __expf(e);
                sumex += ex;
                uint4 hv = *(const uint4*)&g_hl16[(size_t)s * DIM + lw * 8];
                const __half2* hp = (const __half2*)&hv;
#pragma unroll
                for (int q = 0; q < 4; q++) {
                    float2 pp = __half22float2(hp[q]);
                    acc[q * 2]     = fmaf(ex, pp.x, acc[q * 2]);
                    acc[q * 2 + 1] = fmaf(ex, pp.y, acc[q * 2 + 1]);
                }
            }
        }
    }
    sumex += __shfl_xor_sync(0xffffffffu, sumex, 16);
#pragma unroll
    for (int j = 0; j < 8; j++) acc[j] += __shfl_xor_sync(0xffffffffu, acc[j], 16);

    if (hw == 0) {
        float inv = 1.0f / (sumex + 1e-16f);
        float4 b0 = *(const float4*)&bias[lw * 8];
        float4 b1 = *(const float4*)&bias[lw * 8 + 4];
        float4 o0, o1;
        o0.x = silu_f(acc[0] * inv + b0.x);
        o0.y = silu_f(acc[1] * inv + b0.y);
        o0.z = silu_f(acc[2] * inv + b0.z);
        o0.w = silu_f(acc[3] * inv + b0.w);
        o1.x = silu_f(acc[4] * inv + b1.x);
        o1.y = silu_f(acc[5] * inv + b1.y);
        o1.z = silu_f(acc[6] * inv + b1.z);
        o1.w = silu_f(acc[7] * inv + b1.w);
        *(float4*)&g_h[(size_t)n * DIM + lw * 8]     = o0;
        *(float4*)&g_h[(size_t)n * DIM + lw * 8 + 4] = o1;
    }
}

// ---------------- pool / readout bodies ----------------
__device__ __forceinline__ void pool_chunk(const int* __restrict__ batch, int c, int tid) {
    if (tid >= 128) return;
    int d0 = tid;
    int r0 = c * 512;
    if (r0 >= NNODES) return;
    int rend = min(r0 + 512, NNODES);
    int cur = __ldg(&batch[r0]);
    float sum = 0.0f;
    for (int n = r0; n < rend; n++) {
        int g = __ldg(&batch[n]);
        if (g != cur) {
            atomicAdd(&g_pooled[cur * DIM + d0], sum);
            sum = 0.0f;
            cur = g;
        }
        sum += g_h[(size_t)n * DIM + d0];
    }
    atomicAdd(&g_pooled[cur * DIM + d0], sum);
}

__device__ __forceinline__ void readout_body(const float* __restrict__ bw,
                                             const float* __restrict__ sw,
                                             const float* __restrict__ sc,
                                             float* __restrict__ out,
                                             int g, int tid, char* dsm) {
    float* feat = (float*)dsm;              // 4KB
    float* sred = (float*)(dsm + 16384);    // NCLS*4 floats
    int t = tid;
    if (t < 128) {
        float xv = g_pooled[g * DIM + t];
        feat[t] = xv / (1.0f + expf(-xv));
        float bs[7];
        bsplines7(xv, bs);
#pragma unroll
        for (int b = 0; b < 7; b++) feat[DIM + t * 7 + b] = bs[b];
    }
    __syncthreads();

    if (t < 128) {
        float accv[NCLS];
#pragma unroll
        for (int o = 0; o < NCLS; o++) accv[o] = 0.0f;
#pragma unroll
        for (int kk = 0; kk < 8; kk++) {
            int k = kk * DIM + t;
            float f = feat[k];
            if (k < DIM) {
#pragma unroll
                for (int o = 0; o < NCLS; o++) accv[o] += f * bw[o * DIM + k];
            } else {
                int j = (k - DIM) / 7, b = (k - DIM) % 7;
#pragma unroll
                for (int o = 0; o < NCLS; o++)
                    accv[o] += f * sw[o * DIM * NB + j * NB + b] * sc[o * DIM + j];
            }
        }
        int lane = t & 31, warp = t >> 5;
#pragma unroll
        for (int o = 0; o < NCLS; o++) {
            float v = accv[o];
#pragma unroll
            for (int off = 16; off >= 1; off >>= 1) v += __shfl_xor_sync(0xffffffffu, v, off);
            if (lane == 0) sred[o * 4 + warp] = v;
        }
    }
    __syncthreads();
    if (t == 0) {
        float lg[NCLS];
        float mx = -1e30f;
#pragma unroll
        for (int o = 0; o < NCLS; o++) {
            lg[o] = sred[o * 4] + sred[o * 4 + 1] + sred[o * 4 + 2] + sred[o * 4 + 3];
            mx = fmaxf(mx, lg[o]);
        }
        float se = 0.0f;
#pragma unroll
        for (int o = 0; o < NCLS; o++) se += expf(lg[o] - mx);
        float lse = logf(se) + mx;
#pragma unroll
        for (int o = 0; o < NCLS; o++) out[g * NCLS + o] = lg[o] - lse;
    }
}

// ---------------- persistent megakernel: edge0|gemm1|edge1|gemm2|edge2|pool|readout ----
__global__ void __launch_bounds__(256, 2) mega_kernel(
    const int* __restrict__ batch,
    const float* __restrict__ att_src, const float* __restrict__ att_dst,
    const float* __restrict__ bias,
    const float* __restrict__ ro_bw, const float* __restrict__ ro_sw,
    const float* __restrict__ ro_sc, float* __restrict__ out) {
    __shared__ char dsm[SMEM_BYTES];
    int bid = blockIdx.x, tid = threadIdx.x;
    int nb = gridDim.x;
    int wid = tid >> 5, lane = tid & 31;
    int gen = *(volatile int*)&g_bar_gen;

    // edge layer 0 (inputs produced by standalone layer-0 GEMM)
    {
        int gw = bid * 8 + wid, nw = nb * 8;
        for (int n = gw; n < NNODES; n += nw) edge_node_body(bias, n, lane);
    }
    gbar(nb, gen);

    for (int l = 1; l < NLAYER; l++) {
        const float* aS = att_src + (size_t)l * DIM;
        const float* aD = att_dst + (size_t)l * DIM;
        const __half* W = g_W16 + (size_t)l * KDIM * DIM;
        for (int t = bid; t < MTILES; t += nb)
            gemm_tile_body(g_h, aS, aD, W, dsm, t * 128);
        gbar(nb, gen);
        int gw = bid * 8 + wid, nw = nb * 8;
        const float* bl = bias + (size_t)l * DIM;
        for (int n = gw; n < NNODES; n += nw) edge_node_body(bl, n, lane);
        gbar(nb, gen);
    }

    for (int c = bid; c < POOL_CHUNKS; c += nb) pool_chunk(batch, c, tid);
    gbar(nb, gen);

    if (bid < NGR) readout_body(ro_bw, ro_sw, ro_sc, out, bid, tid, dsm);
}

// ---------------- launch ----------------
extern "C" void kernel_launch(void* const* d_in, const int* in_sizes, int n_in,
                              void* d_out, int out_size) {
    const float* x        = (const float*)d_in[0];
    const int*   ei       = (const int*)d_in[1];
    const int*   batch    = (const int*)d_in[2];
    const float* base_w   = (const float*)d_in[3];
    const float* spline_w = (const float*)d_in[4];
    const float* scaler   = (const float*)d_in[5];
    const float* att_src  = (const float*)d_in[6];
    const float* att_dst  = (const float*)d_in[7];
    const float* bias     = (const float*)d_in[8];
    const float* ro_bw    = (const float*)d_in[9];
    const float* ro_sw    = (const float*)d_in[10];
    const float* ro_sc    = (const float*)d_in[11];
    float* out = (float*)d_out;

    cudaFuncSetAttribute(fkan_gemm_mma, cudaFuncAttributeMaxDynamicSharedMemorySize, SMEM_BYTES);

    float* poolp = nullptr;
    int* degp = nullptr;
    __half* wp = nullptr;
    cudaGetSymbolAddress((void**)&poolp, g_pooled);
    cudaGetSymbolAddress((void**)&degp, g_deg);
    cudaGetSymbolAddress((void**)&wp, g_W16);

    static cudaStream_t s_side = nullptr;
    static cudaEvent_t ev_fork = nullptr, ev_join = nullptr;
    static int s_nblocks = 0;
    if (s_side == nullptr) {
        cudaStreamCreateWithFlags(&s_side, cudaStreamNonBlocking);
        cudaEventCreateWithFlags(&ev_fork, cudaEventDisableTiming);
        cudaEventCreateWithFlags(&ev_join, cudaEventDisableTiming);
        int smc = 0;
        cudaDeviceGetAttribute(&smc, cudaDevAttrMultiProcessorCount, 0);
        s_nblocks = smc * 2;   // guaranteed resident with __launch_bounds__(256,2) + 32KB smem
    }

    const int E_BLOCKS = (ETOT + 255) / 256;

    // ---- fork: CSR build + pooled zero on side stream ----
    cudaEventRecord(ev_fork, 0);
    cudaStreamWaitEvent(s_side, ev_fork, 0);
    cudaMemsetAsync(degp, 0, NNODES * sizeof(int), s_side);
    deg_count_kernel<<<E_BLOCKS, 256, 0, s_side>>>(ei);
    scan1_kernel<<<SCAN_BLOCKS, 1024, 0, s_side>>>();
    scan2_kernel<<<1, 32, 0, s_side>>>();
    scan3_kernel<<<SCAN_BLOCKS, 1024, 0, s_side>>>();
    scatter_kernel<<<E_BLOCKS, 256, 0, s_side>>>(ei);
    cudaMemsetAsync(poolp, 0, (size_t)NGR * DIM * sizeof(float), s_side);
    cudaEventRecord(ev_join, s_side);

    // ---- main stream: pack all layers + layer-0 GEMM (overlaps CSR) ----
    pack_w_kernel<<<(NLAYER * KDIM * DIM + 255) / 256, 256>>>(base_w, spline_w, scaler);
    fkan_gemm_mma<<<MTILES, 256, SMEM_BYTES>>>(x, att_src, att_dst, wp);

    // join, then the persistent megakernel does everything else
    cudaStreamWaitEvent(0, ev_join, 0);
    mega_kernel<<<s_nblocks, 256>>>(batch, att_src, att_dst, bias,
                                    ro_bw, ro_sw, ro_sc, out);
}

// round 17
// speedup vs baseline: 1.0894x; 1.0894x over previous
#include <cuda_runtime.h>
#include <cuda_fp16.h>
#include <cstdint>

#define NNODES 50000
#define NEDGE  800000
#define ETOT   850000
#define DIM    128
#define NH     4
#define NB     7
#define KDIM   1024
#define NGR    64
#define NCLS   10
#define NLAYER 3

#define MT64 ((NNODES + 63) / 64)            // 782 tiles of 64 rows
#define SCAN_BLOCKS ((NNODES + 1023) / 1024)  // 49

// ---------------- device scratch ----------------
__device__ __align__(16) __half g_W16[NLAYER * KDIM * DIM];
__device__ __align__(16) float g_h[NNODES * DIM];
__device__ __align__(16) __half g_hl16[NNODES * DIM];
__device__ __align__(16) float g_asrc[NNODES * NH];
__device__ __align__(16) float g_adst[NNODES * NH];
__device__ __align__(16) float g_pooled[NGR * DIM];
// CSR
__device__ int g_deg[NNODES];
__device__ int g_ptr[NNODES + 1];
__device__ int g_cur[NNODES];
__device__ int g_csrc[ETOT];
__device__ int g_bsum[SCAN_BLOCKS];
__device__ int g_boff[SCAN_BLOCKS];

// ---------------- helpers ----------------
__device__ __forceinline__ uint32_t smem_u32(const void* p) {
    uint32_t a;
    asm("{ .reg .u64 t; cvta.to.shared.u64 t, %1; cvt.u32.u64 %0, t; }" : "=r"(a) : "l"(p));
    return a;
}

#define SWZ32(c, r) (((c) ^ ((r) >> 1)) & 3)

__device__ __forceinline__ void ldsm4(uint32_t a, uint32_t& r0, uint32_t& r1,
                                      uint32_t& r2, uint32_t& r3) {
    asm volatile("ldmatrix.sync.aligned.m8n8.x4.shared.b16 {%0,%1,%2,%3}, [%4];"
                 : "=r"(r0), "=r"(r1), "=r"(r2), "=r"(r3) : "r"(a));
}

__device__ __forceinline__ void mma16816(float* d, const uint32_t* a, const uint32_t* b) {
    asm volatile("mma.sync.aligned.m16n8k16.row.col.f32.f16.f16.f32 "
                 "{%0,%1,%2,%3}, {%4,%5,%6,%7}, {%8,%9}, {%0,%1,%2,%3};"
                 : "+f"(d[0]), "+f"(d[1]), "+f"(d[2]), "+f"(d[3])
                 : "r"(a[0]), "r"(a[1]), "r"(a[2]), "r"(a[3]), "r"(b[0]), "r"(b[1]));
}

__device__ __forceinline__ float silu_f(float x) { return x / (1.0f + __expf(-x)); }

// Cox-de Boor recursion (used only in readout)
__device__ __forceinline__ void bsplines7(float x, float* out) {
    float b0[10];
#pragma unroll
    for (int i = 0; i < 10; i++) {
        float g0 = 0.5f * (float)i - 2.5f;
        b0[i] = (x >= g0 && x < g0 + 0.5f) ? 1.0f : 0.0f;
    }
    float b1[9];
#pragma unroll
    for (int i = 0; i < 9; i++) {
        float gi = 0.5f * (float)i - 2.5f;
        b1[i] = (x - gi) * 2.0f * b0[i] + ((gi + 1.0f) - x) * 2.0f * b0[i + 1];
    }
    float b2[8];
#pragma unroll
    for (int i = 0; i < 8; i++) {
        float gi = 0.5f * (float)i - 2.5f;
        b2[i] = (x - gi) * b1[i] + ((gi + 1.5f) - x) * b1[i + 1];
    }
#pragma unroll
    for (int i = 0; i < 7; i++) {
        float gi = 0.5f * (float)i - 2.5f;
        out[i] = ((x - gi) * b2[i] + ((gi + 2.0f) - x) * b2[i + 1]) * (1.0f / 1.5f);
    }
}

__device__ __forceinline__ uint32_t pack_f16x2(float a, float b) {
    uint32_t r;
    asm("cvt.rn.f16x2.f32 %0, %1, %2;" : "=r"(r) : "f"(b), "f"(a));
    return r;
}

// ---------------- CSR build ----------------
__global__ void deg_count_kernel(const int* __restrict__ ei) {
    int e = blockIdx.x * blockDim.x + threadIdx.x;
    if (e >= ETOT) return;
    int d = (e < NEDGE) ? __ldg(&ei[NEDGE + e]) : (e - NEDGE);
    atomicAdd(&g_deg[d], 1);
}

__global__ void scan1_kernel() {
    __shared__ int sh[1024];
    int t = threadIdx.x, b = blockIdx.x;
    int i = b * 1024 + t;
    int v = (i < NNODES) ? g_deg[i] : 0;
    sh[t] = v;
    __syncthreads();
#pragma unroll
    for (int off = 1; off < 1024; off <<= 1) {
        int add = (t >= off) ? sh[t - off] : 0;
        __syncthreads();
        sh[t] += add;
        __syncthreads();
    }
    if (i < NNODES) g_ptr[i] = sh[t] - v;
    if (t == 1023) g_bsum[b] = sh[t];
}

__global__ void scan2_kernel() {
    if (threadIdx.x == 0) {
        int run = 0;
        for (int b = 0; b < SCAN_BLOCKS; b++) { g_boff[b] = run; run += g_bsum[b]; }
        g_ptr[NNODES] = run;
    }
}

__global__ void scan3_kernel() {
    int t = threadIdx.x, b = blockIdx.x;
    int i = b * 1024 + t;
    if (i < NNODES) {
        int p = g_ptr[i] + g_boff[b];
        g_ptr[i] = p;
        g_cur[i] = p;
    }
}

__global__ void scatter_kernel(const int* __restrict__ ei) {
    int e = blockIdx.x * blockDim.x + threadIdx.x;
    if (e >= ETOT) return;
    int s, d;
    if (e < NEDGE) { s = __ldg(&ei[e]); d = __ldg(&ei[NEDGE + e]); }
    else           { s = e - NEDGE; d = s; }
    int pos = atomicAdd(&g_cur[d], 1);
    g_csrc[pos] = s;
}

// ---------------- weight pack (all 3 layers, once, fp16) ----------------
__global__ void pack_w_kernel(const float* __restrict__ bw,
                              const float* __restrict__ sw,
                              const float* __restrict__ sc) {
    int idx = blockIdx.x * blockDim.x + threadIdx.x;
    if (idx >= NLAYER * KDIM * DIM) return;
    int l = idx >> 17;
    int rem = idx & (KDIM * DIM - 1);
    int n = rem >> 10, k = rem & 1023;
    int j = k >> 3, f = k & 7;
    const float* bwl = bw + (size_t)l * DIM * DIM;
    const float* swl = sw + (size_t)l * DIM * DIM * NB;
    const float* scl = sc + (size_t)l * DIM * DIM;
    float v;
    if (f == 0) v = bwl[n * DIM + j];
    else        v = swl[(n * DIM + j) * NB + (f - 1)] * scl[n * DIM + j];
    g_W16[idx] = __float2half_rn(v);
}

// ---------------- fused KAN-GEMM: M=64 tiles, fp16 mma, double-buffered ----------------
// Buffer (12KB): A[0,4K) = 64 rows x 64B, B[4K,12K) = 128 rows x 64B
#define SMEM_BYTES 24576

__device__ __forceinline__ void build_chunk64(const float* __restrict__ in,
                                              const __half* __restrict__ W16,
                                              char* buf, int m0, int tid, int cc) {
    char* Ab = buf;
    char* Bb = buf + 4096;

    // B weights: 2x 16B chunks per thread (128 n-rows x 64B / 256 threads)
    int n = tid >> 1, half = tid & 1;
    const uint4* wh = (const uint4*)(W16 + (size_t)n * KDIM + cc * 32 + half * 16);
    uint4 bh0 = wh[0], bh1 = wh[1];

    // A features: 1 eval per thread (row = tid&63, col c = tid>>6)
    int row = tid & 63, c = tid >> 6;
    int grow = m0 + row;
    float xv = (grow < NNODES) ? __ldg(&in[(size_t)grow * DIM + cc * 4 + c]) : 0.0f;
    {
        uint32_t off = row * 64 + (SWZ32(c, row) << 4);

        float sv = silu_f(xv);
        uint32_t sp = pack_f16x2(sv, 0.0f);
        *(uint4*)(Ab + off) = make_uint4(sp & 0xFFFFu, 0u, 0u, 0u);

        float u = fmaf(2.0f, xv, 5.0f);
        float cf = floorf(u);
        float t = u - cf;
        bool inr = (u >= 0.0f) && (u < 10.0f);
        int cell = (int)cf;
        float t2 = t * t, t3 = t2 * t, s1 = 1.0f - t;
        const float i6 = 1.0f / 6.0f;
        float w[4];
        w[0] = t3 * i6;
        w[1] = fmaf(-3.0f, t3, fmaf(3.0f, t2, fmaf(3.0f, t, 1.0f))) * i6;
        w[2] = fmaf(3.0f, t3, fmaf(-6.0f, t2, 4.0f)) * i6;
        w[3] = s1 * s1 * s1 * i6;
#pragma unroll
        for (int m = 0; m < 4; m++) {
            int j = cell - m;
            if (inr && j >= 0 && j <= 6) {
                __half hw = __float2half_rn(w[m]);
                *(uint16_t*)(Ab + off + 2 * (j + 1)) = __half_as_ushort(hw);
            }
        }
    }
#pragma unroll
    for (int q = 0; q < 2; q++) {
        int bc = half * 2 + q;
        uint32_t off = n * 64 + (SWZ32(bc, n) << 4);
        *(uint4*)(Bb + off) = q ? bh1 : bh0;
    }
}

__global__ void __launch_bounds__(256, 3) fkan_gemm_mma(const float* __restrict__ in,
                                                        const float* __restrict__ attS,
                                                        const float* __restrict__ attD,
                                                        const __half* __restrict__ W16) {
    extern __shared__ char dsm[];
    int tid = threadIdx.x;
    int wid = tid >> 5, lane = tid & 31;
    int m0 = blockIdx.x * 64;
    int warpM = wid & 3, warpN = wid >> 2;   // 16 rows x 64 cols per warp
    uint32_t ubase = smem_u32(dsm);

    int tg = lane >> 3, tr = lane & 7;

    float acc[8][4];
#pragma unroll
    for (int j = 0; j < 8; j++)
#pragma unroll
        for (int q = 0; q < 4; q++) acc[j][q] = 0.0f;

    build_chunk64(in, W16, dsm, m0, tid, 0);
    __syncthreads();

    for (int cc = 0; cc < 32; cc++) {
        int p = cc & 1;
        uint32_t uA = ubase + p * 12288;
        uint32_t uB = uA + 4096;

#pragma unroll
        for (int ks = 0; ks < 2; ks++) {
            uint32_t ah[4];
            {
                int arow = warpM * 16 + (tg & 1) * 8 + tr;
                int ac = ks * 2 + (tg >> 1);
                uint32_t aoff = arow * 64 + (SWZ32(ac, arow) << 4);
                ldsm4(uA + aoff, ah[0], ah[1], ah[2], ah[3]);
            }
#pragma unroll
            for (int gh = 0; gh < 2; gh++) {
                uint32_t bh[2][4];
#pragma unroll
                for (int gg = 0; gg < 2; gg++) {
                    int g = gh * 2 + gg;
                    int brow = warpN * 64 + g * 16 + (tg >> 1) * 8 + tr;
                    int bc = ks * 2 + (tg & 1);
                    uint32_t boff = brow * 64 + (SWZ32(bc, brow) << 4);
                    ldsm4(uB + boff, bh[gg][0], bh[gg][1], bh[gg][2], bh[gg][3]);
                }
#pragma unroll
                for (int gg = 0; gg < 2; gg++) {
                    int g = gh * 2 + gg;
                    mma16816(acc[2 * g],     ah, &bh[gg][0]);
                    mma16816(acc[2 * g + 1], ah, &bh[gg][2]);
                }
            }
        }

        if (cc < 31)
            build_chunk64(in, W16, dsm + (p ^ 1) * 12288, m0, tid, cc + 1);
        __syncthreads();
    }

    // ---- epilogue: store h (fp16) + fused attention dots ----
    int qd = lane >> 2, ql = lane & 3;
#pragma unroll
    for (int hh = 0; hh < 2; hh++) {
        int row = m0 + warpM * 16 + hh * 8 + qd;
        bool ok = row < NNODES;
        float ps0 = 0.f, pd0 = 0.f, ps1 = 0.f, pd1 = 0.f;
#pragma unroll
        for (int j = 0; j < 8; j++) {
            int col = warpN * 64 + j * 8 + ql * 2;
            float v0 = acc[j][hh * 2 + 0];
            float v1 = acc[j][hh * 2 + 1];
            if (ok) {
                __half2 hv = __floats2half2_rn(v0, v1);
                *(__half2*)&g_hl16[(size_t)row * DIM + col] = hv;
            }
            float s0 = __ldg(&attS[col]), s1 = __ldg(&attS[col + 1]);
            float d0 = __ldg(&attD[col]), d1 = __ldg(&attD[col + 1]);
            float ps = v0 * s0 + v1 * s1;
            float pd = v0 * d0 + v1 * d1;
            if (j < 4) { ps0 += ps; pd0 += pd; } else { ps1 += ps; pd1 += pd; }
        }
#pragma unroll
        for (int o = 1; o <= 2; o <<= 1) {
            ps0 += __shfl_xor_sync(0xffffffffu, ps0, o);
            pd0 += __shfl_xor_sync(0xffffffffu, pd0, o);
            ps1 += __shfl_xor_sync(0xffffffffu, ps1, o);
            pd1 += __shfl_xor_sync(0xffffffffu, pd1, o);
        }
        if (ql == 0 && ok) {
            int hbase = warpN * 2;
            g_asrc[row * 4 + hbase]     = ps0;
            g_asrc[row * 4 + hbase + 1] = ps1;
            g_adst[row * 4 + hbase]     = pd0;
            g_adst[row * 4 + hbase + 1] = pd1;
        }
    }
}

// ---------------- fused pull-mode edge phase (split-lane, 2 edges/iter) ----------------
__global__ void __launch_bounds__(256) edge_fused_kernel(const float* __restrict__ bias) {
    int gid = blockIdx.x * blockDim.x + threadIdx.x;
    int n = gid >> 5, lane = gid & 31;
    if (n >= NNODES) return;
    int start = __ldg(&g_ptr[n]);
    int end   = __ldg(&g_ptr[n + 1]);
    int hw = lane >> 4;
    int lw = lane & 15;
    int hh = lw >> 2;
    float bd = g_adst[n * 4 + hh];

    float acc[8];
#pragma unroll
    for (int j = 0; j < 8; j++) acc[j] = 0.0f;
    float sumex = 0.0f;

    for (int j0 = start; j0 < end; j0 += 32) {
        int m = min(32, end - j0);
        int s_pref = (j0 + lane < end) ? __ldg(&g_csrc[j0 + lane]) : 0;
#pragma unroll 4
        for (int i = 0; i < m; i += 2) {
            int idx = i + hw;
            int s = __shfl_sync(0xffffffffu, s_pref, idx & 31);
            if (idx < m) {
                float a = __ldg(&g_asrc[s * 4 + hh]);
                float e = a + bd;
                e = (e > 0.f) ? e : 0.2f * e;
                float ex = __expf(e);
                sumex += ex;
                uint4 hv = *(const uint4*)&g_hl16[(size_t)s * DIM + lw * 8];
                const __half2* hp = (const __half2*)&hv;
#pragma unroll
                for (int q = 0; q < 4; q++) {
                    float2 pp = __half22float2(hp[q]);
                    acc[q * 2]     = fmaf(ex, pp.x, acc[q * 2]);
                    acc[q * 2 + 1] = fmaf(ex, pp.y, acc[q * 2 + 1]);
                }
            }
        }
    }
    sumex += __shfl_xor_sync(0xffffffffu, sumex, 16);
#pragma unroll
    for (int j = 0; j < 8; j++) acc[j] += __shfl_xor_sync(0xffffffffu, acc[j], 16);

    if (hw == 0) {
        float inv = 1.0f / (sumex + 1e-16f);
        float4 b0 = *(const float4*)&bias[lw * 8];
        float4 b1 = *(const float4*)&bias[lw * 8 + 4];
        float4 o0, o1;
        o0.x = silu_f(acc[0] * inv + b0.x);
        o0.y = silu_f(acc[1] * inv + b0.y);
        o0.z = silu_f(acc[2] * inv + b0.z);
        o0.w = silu_f(acc[3] * inv + b0.w);
        o1.x = silu_f(acc[4] * inv + b1.x);
        o1.y = silu_f(acc[5] * inv + b1.y);
        o1.z = silu_f(acc[6] * inv + b1.z);
        o1.w = silu_f(acc[7] * inv + b1.w);
        *(float4*)&g_h[(size_t)n * DIM + lw * 8]     = o0;
        *(float4*)&g_h[(size_t)n * DIM + lw * 8 + 4] = o1;
    }
}

// ---------------- pooling + readout ----------------
__global__ void pool_kernel(const int* __restrict__ batch) {
    int d0 = threadIdx.x;
    int r0 = blockIdx.x * 512;
    if (r0 >= NNODES) return;
    int rend = min(r0 + 512, NNODES);
    int cur = __ldg(&batch[r0]);
    float sum = 0.0f;
    for (int n = r0; n < rend; n++) {
        int g = __ldg(&batch[n]);
        if (g != cur) {
            atomicAdd(&g_pooled[cur * DIM + d0], sum);
            sum = 0.0f;
            cur = g;
        }
        sum += g_h[(size_t)n * DIM + d0];
    }
    atomicAdd(&g_pooled[cur * DIM + d0], sum);
}

__global__ void readout_kernel(const float* __restrict__ bw,
                               const float* __restrict__ sw,
                               const float* __restrict__ sc,
                               float* __restrict__ out) {
    __shared__ float feat[KDIM];
    __shared__ float sred[NCLS * 4];
    int g = blockIdx.x, t = threadIdx.x;
    float xv = g_pooled[g * DIM + t];
    feat[t] = xv / (1.0f + expf(-xv));
    float bs[7];
    bsplines7(xv, bs);
#pragma unroll
    for (int b = 0; b < 7; b++) feat[DIM + t * 7 + b] = bs[b];
    __syncthreads();

    float accv[NCLS];
#pragma unroll
    for (int o = 0; o < NCLS; o++) accv[o] = 0.0f;
#pragma unroll
    for (int kk = 0; kk < 8; kk++) {
        int k = kk * DIM + t;
        float f = feat[k];
        if (k < DIM) {
#pragma unroll
            for (int o = 0; o < NCLS; o++) accv[o] += f * bw[o * DIM + k];
        } else {
            int j = (k - DIM) / 7, b = (k - DIM) % 7;
#pragma unroll
            for (int o = 0; o < NCLS; o++)
                accv[o] += f * sw[o * DIM * NB + j * NB + b] * sc[o * DIM + j];
        }
    }
    int lane = t & 31, warp = t >> 5;
#pragma unroll
    for (int o = 0; o < NCLS; o++) {
        float v = accv[o];
#pragma unroll
        for (int off = 16; off >= 1; off >>= 1) v += __shfl_xor_sync(0xffffffffu, v, off);
        if (lane == 0) sred[o * 4 + warp] = v;
    }
    __syncthreads();
    if (t == 0) {
        float lg[NCLS];
        float mx = -1e30f;
#pragma unroll
        for (int o = 0; o < NCLS; o++) {
            lg[o] = sred[o * 4] + sred[o * 4 + 1] + sred[o * 4 + 2] + sred[o * 4 + 3];
            mx = fmaxf(mx, lg[o]);
        }
        float se = 0.0f;
#pragma unroll
        for (int o = 0; o < NCLS; o++) se += expf(lg[o] - mx);
        float lse = logf(se) + mx;
#pragma unroll
        for (int o = 0; o < NCLS; o++) out[g * NCLS + o] = lg[o] - lse;
    }
}

// ---------------- launch ----------------
extern "C" void kernel_launch(void* const* d_in, const int* in_sizes, int n_in,
                              void* d_out, int out_size) {
    const float* x        = (const float*)d_in[0];
    const int*   ei       = (const int*)d_in[1];
    const int*   batch    = (const int*)d_in[2];
    const float* base_w   = (const float*)d_in[3];
    const float* spline_w = (const float*)d_in[4];
    const float* scaler   = (const float*)d_in[5];
    const float* att_src  = (const float*)d_in[6];
    const float* att_dst  = (const float*)d_in[7];
    const float* bias     = (const float*)d_in[8];
    const float* ro_bw    = (const float*)d_in[9];
    const float* ro_sw    = (const float*)d_in[10];
    const float* ro_sc    = (const float*)d_in[11];
    float* out = (float*)d_out;

    cudaFuncSetAttribute(fkan_gemm_mma, cudaFuncAttributeMaxDynamicSharedMemorySize, SMEM_BYTES);

    float *hbuf = nullptr, *poolp = nullptr;
    int* degp = nullptr;
    __half* wp = nullptr;
    cudaGetSymbolAddress((void**)&hbuf, g_h);
    cudaGetSymbolAddress((void**)&poolp, g_pooled);
    cudaGetSymbolAddress((void**)&degp, g_deg);
    cudaGetSymbolAddress((void**)&wp, g_W16);

    static cudaStream_t s_side = nullptr;
    static cudaEvent_t ev_fork = nullptr, ev_join = nullptr;
    if (s_side == nullptr) {
        cudaStreamCreateWithFlags(&s_side, cudaStreamNonBlocking);
        cudaEventCreateWithFlags(&ev_fork, cudaEventDisableTiming);
        cudaEventCreateWithFlags(&ev_join, cudaEventDisableTiming);
    }

    const int E_BLOCKS = (ETOT + 255) / 256;

    // ---- fork: CSR build + pooled zero on side stream ----
    cudaEventRecord(ev_fork, 0);
    cudaStreamWaitEvent(s_side, ev_fork, 0);
    cudaMemsetAsync(degp, 0, NNODES * sizeof(int), s_side);
    deg_count_kernel<<<E_BLOCKS, 256, 0, s_side>>>(ei);
    scan1_kernel<<<SCAN_BLOCKS, 1024, 0, s_side>>>();
    scan2_kernel<<<1, 32, 0, s_side>>>();
    scan3_kernel<<<SCAN_BLOCKS, 1024, 0, s_side>>>();
    scatter_kernel<<<E_BLOCKS, 256, 0, s_side>>>(ei);
    cudaMemsetAsync(poolp, 0, (size_t)NGR * DIM * sizeof(float), s_side);
    cudaEventRecord(ev_join, s_side);

    // ---- main stream: pack all layers, layer-0 GEMM (independent of CSR) ----
    pack_w_kernel<<<(NLAYER * KDIM * DIM + 255) / 256, 256>>>(base_w, spline_w, scaler);
    fkan_gemm_mma<<<MT64, 256, SMEM_BYTES>>>(x, att_src, att_dst, wp);

    // join: edge phase needs the CSR
    cudaStreamWaitEvent(0, ev_join, 0);
    edge_fused_kernel<<<(NNODES * 32 + 255) / 256, 256>>>(bias);

    for (int l = 1; l < NLAYER; l++) {
        fkan_gemm_mma<<<MT64, 256, SMEM_BYTES>>>(
            hbuf, att_src + (size_t)l * DIM, att_dst + (size_t)l * DIM,
            wp + (size_t)l * KDIM * DIM);
        edge_fused_kernel<<<(NNODES * 32 + 255) / 256, 256>>>(bias + (size_t)l * DIM);
    }
    pool_kernel<<<(NNODES + 511) / 512, DIM>>>(batch);
    readout_kernel<<<NGR, DIM>>>(ro_bw, ro_sw, ro_sc, out);
}